// round 12
// baseline (speedup 1.0000x reference)
#include <cuda_runtime.h>
#include <cstdint>

// CRPS loss — 2 threads per pixel (split the 136-op pixel workload 68/68).
//   term1 = mean_i |s_i - y| ; term2 = sum_{i<j}|s_i - s_j| / 256
//   out   = mean_pixels (term1 - term2)
//
// samples: [16, 4, 1, 256, 256] f32 -> 16 planes of 262144 floats
// target:  [4, 1, 256, 256]     f32 -> 262144 floats
//
// 2048 CTAs x 256 threads. Threads tid and tid+128 handle the SAME pixel:
// role 0 = term1(i<8) + even-numbered pairs, role 1 = term1(i>=8) + odd pairs.
// Their duplicate loads hit the same 128B lines (same CTA, issued together)
// -> L1 merges them, DRAM traffic unchanged. Per-warp work halves and warp
// count doubles (16384 warps), halving exposed memory latency.

#define NS      16
#define NPIX    (4 * 1 * 256 * 256)     // 262144
#define PIX_BLK 128
#define THREADS 256
#define BLOCKS  (NPIX / PIX_BLK)        // 2048

__device__ float        g_partial[BLOCKS];
__device__ unsigned int g_done = 0;

__global__ __launch_bounds__(THREADS) void crps_fused_kernel(
    const float* __restrict__ samples,
    const float* __restrict__ target,
    float* __restrict__ out)
{
    const int tid  = threadIdx.x;
    const int role = tid >> 7;                       // 0 or 1
    const int p    = blockIdx.x * PIX_BLK + (tid & 127);

    // ---- loads: 17 x LDG.32 per thread; role pair shares lines via L1 ----
    float s[NS];
#pragma unroll
    for (int i = 0; i < NS; i++)
        s[i] = samples[(size_t)i * NPIX + p];
    const float y = target[p];

    float t1a = 0.0f, t1b = 0.0f;
    float t2[4] = {0.0f, 0.0f, 0.0f, 0.0f};

    if (role == 0) {
        // term1, samples 0..7
#pragma unroll
        for (int i = 0; i < 8; i += 2) {
            t1a += fabsf(s[i]     - y);
            t1b += fabsf(s[i + 1] - y);
        }
        // even-numbered pairs (60 of 120)
        int c = 0;
#pragma unroll
        for (int i = 0; i < NS; i++) {
#pragma unroll
            for (int j = i + 1; j < NS; j++) {
                if ((c & 1) == 0)
                    t2[(c >> 1) & 3] += fabsf(s[i] - s[j]);
                c++;
            }
        }
    } else {
        // term1, samples 8..15
#pragma unroll
        for (int i = 8; i < NS; i += 2) {
            t1a += fabsf(s[i]     - y);
            t1b += fabsf(s[i + 1] - y);
        }
        // odd-numbered pairs (60 of 120)
        int c = 0;
#pragma unroll
        for (int i = 0; i < NS; i++) {
#pragma unroll
            for (int j = i + 1; j < NS; j++) {
                if ((c & 1) == 1)
                    t2[(c >> 1) & 3] += fabsf(s[i] - s[j]);
                c++;
            }
        }
    }

    // Partial CRPS contribution (linear, so role-split sums correctly).
    float val = (t1a + t1b) * (1.0f / NS)
              - ((t2[0] + t2[1]) + (t2[2] + t2[3])) * (1.0f / (NS * NS));

    // ---- block reduction (8 warps) ----
    __shared__ float warp_sum[THREADS / 32];
    float w = val;
#pragma unroll
    for (int off = 16; off > 0; off >>= 1)
        w += __shfl_down_sync(0xFFFFFFFFu, w, off);
    if ((tid & 31) == 0) warp_sum[tid >> 5] = w;
    __syncthreads();

    __shared__ bool is_last;
    if (tid == 0) {
        float b = 0.0f;
#pragma unroll
        for (int k = 0; k < THREADS / 32; k++) b += warp_sum[k];
        g_partial[blockIdx.x] = b;
        __threadfence();
        unsigned int ticket = atomicAdd(&g_done, 1u);
        is_last = (ticket == BLOCKS - 1);
    }
    __syncthreads();

    // ---- last block folds the 2048 partials ----
    if (is_last) {
        float acc = 0.0f;
#pragma unroll
        for (int k = 0; k < BLOCKS / THREADS; k++)
            acc += g_partial[tid + k * THREADS];
#pragma unroll
        for (int off = 16; off > 0; off >>= 1)
            acc += __shfl_down_sync(0xFFFFFFFFu, acc, off);
        if ((tid & 31) == 0) warp_sum[tid >> 5] = acc;
        __syncthreads();
        if (tid == 0) {
            float total = 0.0f;
#pragma unroll
            for (int k = 0; k < THREADS / 32; k++) total += warp_sum[k];
            out[0] = total * (1.0f / NPIX);
            g_done = 0;                  // reset for next graph replay
        }
    }
}

extern "C" void kernel_launch(void* const* d_in, const int* in_sizes, int n_in,
                              void* d_out, int out_size)
{
    const float* samples = (const float*)d_in[0];
    const float* target  = (const float*)d_in[1];
    crps_fused_kernel<<<BLOCKS, THREADS>>>(samples, target, (float*)d_out);
}

// round 13
// speedup vs baseline: 1.5952x; 1.5952x over previous
#include <cuda_runtime.h>
#include <cstdint>

// CRPS loss — SASS-pinned 34-load burst (asm volatile) + packed f32x2 compute.
//   term1 = mean_i |s_i - y| ; term2 = sum_{i<j}|s_i - s_j| / 256
//   out   = mean_pixels (term1 - term2)
//
// samples: [16, 4, 1, 256, 256] f32 -> 16 planes of 262144 floats (1 MB/plane)
// target:  [4, 1, 256, 256]     f32 -> 262144 floats
//
// 512 CTAs x 128 threads (65K threads — the low-launch-overhead shape).
// Each thread owns TWO float2 groups (4 pixels). All 34 LDG.64 are emitted as
// asm volatile with immediate plane offsets so ptxas CANNOT split the burst:
// one exposed memory wait per warp, everything else is issue-dense compute.

#define NS      16
#define NPIX    (4 * 1 * 256 * 256)     // 262144
#define THREADS 128
#define BLOCKS  512
#define HALF    (BLOCKS * THREADS)      // 65536 float2 groups per half
#define PLANE_B (NPIX * 4)              // 1048576 bytes per sample plane

__device__ float        g_partial[BLOCKS];
__device__ unsigned int g_done = 0;

// ---- packed f32x2 helpers (sm_103a) ----
__device__ __forceinline__ uint64_t fadd2(uint64_t a, uint64_t b) {
    uint64_t r; asm("add.rn.f32x2 %0, %1, %2;" : "=l"(r) : "l"(a), "l"(b)); return r;
}
__device__ __forceinline__ uint64_t ffma2(uint64_t a, uint64_t b, uint64_t c) {
    uint64_t r; asm("fma.rn.f32x2 %0, %1, %2, %3;" : "=l"(r) : "l"(a), "l"(b), "l"(c)); return r;
}
__device__ __forceinline__ uint64_t fabs2(uint64_t a) {
    return a & 0x7FFFFFFF7FFFFFFFULL;       // sign-clear both lanes (alu pipe)
}
__device__ __forceinline__ float2 unpack2(uint64_t v) {
    float lo, hi; asm("mov.b64 {%0, %1}, %2;" : "=f"(lo), "=f"(hi) : "l"(v));
    return make_float2(lo, hi);
}
#define NEG_ONE2 0xBF800000BF800000ULL      // {-1.0f, -1.0f}
#define PAIR(acc, a, b) (acc) = fadd2((acc), fabs2(ffma2((b), NEG_ONE2, (a))))

// Pinned LDG.64 with immediate byte offset (cannot be reordered/split by ptxas).
#define LDG64(dst, base, OFF) \
    asm volatile("ld.global.nc.b64 %0, [%1+" #OFF "];" : "=l"(dst) : "l"(base))

__global__ __launch_bounds__(THREADS, 1) void crps_fused_kernel(
    const float* __restrict__ samples,
    const float* __restrict__ target,
    float* __restrict__ out)
{
    const int tid = threadIdx.x;
    const int v0  = blockIdx.x * THREADS + tid;     // group A (2 pixels)
    // group B = v0 + HALF  -> byte offset +524288 within each plane

    const char* base_lo = (const char*)samples + (size_t)v0 * 8;            // planes 0-7
    const char* base_hi = base_lo + (size_t)8 * PLANE_B;                    // planes 8-15
    const char* base_t  = (const char*)target  + (size_t)v0 * 8;

    // ---- 34-load burst, SASS-pinned ----
    uint64_t sa[NS], sb[NS], ya, yb;
    LDG64(sa[ 0], base_lo,       0); LDG64(sa[ 1], base_lo, 1048576);
    LDG64(sa[ 2], base_lo, 2097152); LDG64(sa[ 3], base_lo, 3145728);
    LDG64(sa[ 4], base_lo, 4194304); LDG64(sa[ 5], base_lo, 5242880);
    LDG64(sa[ 6], base_lo, 6291456); LDG64(sa[ 7], base_lo, 7340032);
    LDG64(sa[ 8], base_hi,       0); LDG64(sa[ 9], base_hi, 1048576);
    LDG64(sa[10], base_hi, 2097152); LDG64(sa[11], base_hi, 3145728);
    LDG64(sa[12], base_hi, 4194304); LDG64(sa[13], base_hi, 5242880);
    LDG64(sa[14], base_hi, 6291456); LDG64(sa[15], base_hi, 7340032);
    LDG64(sb[ 0], base_lo,  524288); LDG64(sb[ 1], base_lo, 1572864);
    LDG64(sb[ 2], base_lo, 2621440); LDG64(sb[ 3], base_lo, 3670016);
    LDG64(sb[ 4], base_lo, 4718592); LDG64(sb[ 5], base_lo, 5767168);
    LDG64(sb[ 6], base_lo, 6815744); LDG64(sb[ 7], base_lo, 7864320);
    LDG64(sb[ 8], base_hi,  524288); LDG64(sb[ 9], base_hi, 1572864);
    LDG64(sb[10], base_hi, 2621440); LDG64(sb[11], base_hi, 3670016);
    LDG64(sb[12], base_hi, 4718592); LDG64(sb[13], base_hi, 5767168);
    LDG64(sb[14], base_hi, 6815744); LDG64(sb[15], base_hi, 7864320);
    LDG64(ya,     base_t,        0); LDG64(yb,     base_t,   524288);

    // ---- packed compute (identical math to the 10.7us record kernel) ----
    uint64_t t1a = 0, t1b = 0;
#pragma unroll
    for (int i = 0; i < NS; i += 2) {
        PAIR(t1a, sa[i],     ya);
        PAIR(t1b, sa[i + 1], ya);
        PAIR(t1a, sb[i],     yb);
        PAIR(t1b, sb[i + 1], yb);
    }
    uint64_t t2[4] = {0, 0, 0, 0};
    {
        int c = 0;
#pragma unroll
        for (int i = 0; i < NS; i++) {
#pragma unroll
            for (int j = i + 1; j < NS; j++) {
                t2[c & 3]       = fadd2(t2[c & 3],       fabs2(ffma2(sa[j], NEG_ONE2, sa[i])));
                t2[(c + 1) & 3] = fadd2(t2[(c + 1) & 3], fabs2(ffma2(sb[j], NEG_ONE2, sb[i])));
                c += 2;
            }
        }
    }

    const float2 p1 = unpack2(fadd2(t1a, t1b));
    const float2 p2 = unpack2(fadd2(fadd2(t2[0], t2[1]), fadd2(t2[2], t2[3])));
    float val = (p1.x + p1.y) * (1.0f / NS)
              - (p2.x + p2.y) * (1.0f / (NS * NS));

    // ---- block reduction (4 warps) ----
    __shared__ float warp_sum[THREADS / 32];
    float w = val;
#pragma unroll
    for (int off = 16; off > 0; off >>= 1)
        w += __shfl_down_sync(0xFFFFFFFFu, w, off);
    if ((tid & 31) == 0) warp_sum[tid >> 5] = w;
    __syncthreads();

    __shared__ bool is_last;
    if (tid == 0) {
        float b = (warp_sum[0] + warp_sum[1]) + (warp_sum[2] + warp_sum[3]);
        g_partial[blockIdx.x] = b;
        __threadfence();
        unsigned int ticket = atomicAdd(&g_done, 1u);
        is_last = (ticket == BLOCKS - 1);
    }
    __syncthreads();

    // ---- last block folds the 512 partials ----
    if (is_last) {
        float acc = 0.0f;
#pragma unroll
        for (int k = 0; k < BLOCKS / THREADS; k++)
            acc += g_partial[tid + k * THREADS];
#pragma unroll
        for (int off = 16; off > 0; off >>= 1)
            acc += __shfl_down_sync(0xFFFFFFFFu, acc, off);
        if ((tid & 31) == 0) warp_sum[tid >> 5] = acc;
        __syncthreads();
        if (tid == 0) {
            float total = (warp_sum[0] + warp_sum[1]) + (warp_sum[2] + warp_sum[3]);
            out[0] = total * (1.0f / NPIX);
            g_done = 0;                  // reset for next graph replay
        }
    }
}

extern "C" void kernel_launch(void* const* d_in, const int* in_sizes, int n_in,
                              void* d_out, int out_size)
{
    const float* samples = (const float*)d_in[0];
    const float* target  = (const float*)d_in[1];
    crps_fused_kernel<<<BLOCKS, THREADS>>>(samples, target, (float*)d_out);
}